// round 4
// baseline (speedup 1.0000x reference)
#include <cuda_runtime.h>
#include <cuda_fp16.h>
#include <cstdint>

#define S_LEN 2048
#define B_SZ 2
#define DM 1024
#define NH 16
#define DK 64
#define ROWS (B_SZ * S_LEN)   // 4096

// ---------------------------------------------------------------------------
// Scratch (allocation-free __device__ globals)
// ---------------------------------------------------------------------------
__device__ __align__(16) __half g_qh[(size_t)ROWS * DM];
__device__ __align__(16) __half g_kh[(size_t)ROWS * DM];
__device__ __align__(16) __half g_vh[(size_t)ROWS * DM];
__device__ __align__(16) __half g_Wqh[(size_t)DM * DM];
__device__ __align__(16) __half g_Wkh[(size_t)DM * DM];
__device__ __align__(16) __half g_Wvh[(size_t)DM * DM];
__device__ __align__(16) __half g_Woh[(size_t)DM * DM];
__device__ __align__(16) __half g_Qh[(size_t)ROWS * DM];
__device__ __align__(16) __half g_Kh[(size_t)ROWS * DM];
__device__ __align__(16) __half g_Vh[(size_t)ROWS * DM];
__device__ __align__(16) __half g_Ch[(size_t)ROWS * DM];

// ---------------------------------------------------------------------------
// PTX helpers
// ---------------------------------------------------------------------------
__device__ __forceinline__ uint32_t sptr(const void* p) {
    return (uint32_t)__cvta_generic_to_shared(p);
}
__device__ __forceinline__ void ldm_x4(uint32_t& r0, uint32_t& r1,
                                       uint32_t& r2, uint32_t& r3, uint32_t a) {
    asm volatile("ldmatrix.sync.aligned.m8n8.x4.shared.b16 {%0,%1,%2,%3},[%4];\n"
                 : "=r"(r0), "=r"(r1), "=r"(r2), "=r"(r3) : "r"(a));
}
__device__ __forceinline__ void ldm_x4_t(uint32_t& r0, uint32_t& r1,
                                         uint32_t& r2, uint32_t& r3, uint32_t a) {
    asm volatile("ldmatrix.sync.aligned.m8n8.x4.trans.shared.b16 {%0,%1,%2,%3},[%4];\n"
                 : "=r"(r0), "=r"(r1), "=r"(r2), "=r"(r3) : "r"(a));
}
__device__ __forceinline__ void mma16816(float* c, const uint32_t* a,
                                         uint32_t b0, uint32_t b1) {
    asm volatile(
        "mma.sync.aligned.m16n8k16.row.col.f32.f16.f16.f32 "
        "{%0,%1,%2,%3},{%4,%5,%6,%7},{%8,%9},{%0,%1,%2,%3};\n"
        : "+f"(c[0]), "+f"(c[1]), "+f"(c[2]), "+f"(c[3])
        : "r"(a[0]), "r"(a[1]), "r"(a[2]), "r"(a[3]), "r"(b0), "r"(b1));
}
__device__ __forceinline__ uint32_t pack_h2(float x, float y) {
    __half2 h = __floats2half2_rn(x, y);
    return *reinterpret_cast<uint32_t*>(&h);
}
__device__ __forceinline__ void cp16(uint32_t dst, const void* src) {
    asm volatile("cp.async.cg.shared.global [%0],[%1],16;\n" :: "r"(dst), "l"(src));
}
__device__ __forceinline__ void cp_commit() {
    asm volatile("cp.async.commit_group;\n");
}
template <int N>
__device__ __forceinline__ void cp_wait() {
    asm volatile("cp.async.wait_group %0;\n" :: "n"(N));
}
__device__ __forceinline__ float ex2(float x) {
    float y;
    asm("ex2.approx.f32 %0,%1;" : "=f"(y) : "f"(x));
    return y;
}

// ---------------------------------------------------------------------------
// fp32 -> fp16 conversion (vectorized)
// ---------------------------------------------------------------------------
__global__ void f2h(const float4* __restrict__ in, __half2* __restrict__ out, int n4) {
    int i = blockIdx.x * blockDim.x + threadIdx.x;
    if (i < n4) {
        float4 v = in[i];
        out[2 * i]     = __floats2half2_rn(v.x, v.y);
        out[2 * i + 1] = __floats2half2_rn(v.z, v.w);
    }
}

// ---------------------------------------------------------------------------
// HMMA GEMM, cp.async 2-stage pipeline, fused bias.
// C[m][n] = sum_k A[m][k]*W[n][k] + bias[n].  A:[M,K] fp16, W:[N,K] fp16.
// CTA tile 128x128, BK=64, 8 warps (2m x 4n), warp tile 64x32, fp32 accum.
// Dynamic smem: 2 stages x (As 128x72 + Ws 128x72) halfs = 73728 B.
// ---------------------------------------------------------------------------
#define GEMM_STAGE (128 * 72)
#define GEMM_SMEM  (4 * GEMM_STAGE * 2)   // bytes

template <bool HALF_OUT>
__global__ __launch_bounds__(256) void gemm_bias_tc(
    const __half* __restrict__ A, const __half* __restrict__ W,
    const float* __restrict__ bias, void* __restrict__ Cout,
    int M, int N, int K)
{
    extern __shared__ __half sm[];
    __half* Asm = sm;                     // [2][128*72]
    __half* Wsm = sm + 2 * GEMM_STAGE;    // [2][128*72]

    const int tid = threadIdx.x;
    const int warp = tid >> 5, lane = tid & 31;
    const int wm = warp >> 2;
    const int wn = warp & 3;
    const int row0 = blockIdx.y * 128;
    const int col0 = blockIdx.x * 128;

    const int srow = tid >> 3;            // 0..31
    const int scol = (tid & 7) * 8;       // 0..56

    // stage one 64-wide K chunk into smem stage st via cp.async
    auto stage_chunk = [&](int st, int k0) {
        __half* As = Asm + st * GEMM_STAGE;
        __half* Ws = Wsm + st * GEMM_STAGE;
        #pragma unroll
        for (int i = 0; i < 4; i++) {
            const int r = srow + i * 32;
            cp16(sptr(&As[r * 72 + scol]), &A[(size_t)(row0 + r) * K + k0 + scol]);
            cp16(sptr(&Ws[r * 72 + scol]), &W[(size_t)(col0 + r) * K + k0 + scol]);
        }
        cp_commit();
    };

    float acc[4][4][4];
    #pragma unroll
    for (int i = 0; i < 4; i++)
        #pragma unroll
        for (int j = 0; j < 4; j++)
            #pragma unroll
            for (int r = 0; r < 4; r++) acc[i][j][r] = 0.0f;

    const int NCHUNK = K / 64;            // 16
    stage_chunk(0, 0);
    stage_chunk(1, 64);

    for (int c = 0; c < NCHUNK; c++) {
        cp_wait<1>();                     // chunk c arrived (c+1 in flight)
        __syncthreads();

        const int st = c & 1;
        const __half* As = Asm + st * GEMM_STAGE;
        const __half* Ws = Wsm + st * GEMM_STAGE;

        #pragma unroll
        for (int kk = 0; kk < 64; kk += 16) {
            uint32_t af[4][4];
            #pragma unroll
            for (int mt = 0; mt < 4; mt++) {
                const int r = wm * 64 + mt * 16 + (lane & 15);
                const int cc = kk + ((lane >> 4) << 3);
                ldm_x4(af[mt][0], af[mt][1], af[mt][2], af[mt][3],
                       sptr(&As[r * 72 + cc]));
            }
            uint32_t bf[4][2];
            #pragma unroll
            for (int nt = 0; nt < 4; nt += 2) {
                const int g = lane >> 3;
                const int rr = wn * 32 + nt * 8 + ((g >= 2) ? 8 : 0) + (lane & 7);
                const int cc = kk + ((g & 1) << 3);
                ldm_x4(bf[nt][0], bf[nt][1], bf[nt + 1][0], bf[nt + 1][1],
                       sptr(&Ws[rr * 72 + cc]));
            }
            #pragma unroll
            for (int mt = 0; mt < 4; mt++)
                #pragma unroll
                for (int nt = 0; nt < 4; nt++)
                    mma16816(acc[mt][nt], af[mt], bf[nt][0], bf[nt][1]);
        }
        __syncthreads();                  // all reads of stage st done
        if (c + 2 < NCHUNK) stage_chunk(st, (c + 2) * 64);
        else cp_commit();                 // keep group count consistent
    }

    #pragma unroll
    for (int mt = 0; mt < 4; mt++) {
        const int r = row0 + wm * 64 + mt * 16 + (lane >> 2);
        #pragma unroll
        for (int nt = 0; nt < 4; nt++) {
            const int c = col0 + wn * 32 + nt * 8 + ((lane & 3) << 1);
            const float b0 = bias[c], b1 = bias[c + 1];
            if (HALF_OUT) {
                __half* C = (__half*)Cout;
                *(__half2*)&C[(size_t)r * N + c] =
                    __floats2half2_rn(acc[mt][nt][0] + b0, acc[mt][nt][1] + b1);
                *(__half2*)&C[(size_t)(r + 8) * N + c] =
                    __floats2half2_rn(acc[mt][nt][2] + b0, acc[mt][nt][3] + b1);
            } else {
                float* C = (float*)Cout;
                float2 v0 = {acc[mt][nt][0] + b0, acc[mt][nt][1] + b1};
                float2 v1 = {acc[mt][nt][2] + b0, acc[mt][nt][3] + b1};
                *(float2*)&C[(size_t)r * N + c] = v0;
                *(float2*)&C[(size_t)(r + 8) * N + c] = v1;
            }
        }
    }
}

// ---------------------------------------------------------------------------
// Flash attention, HMMA, cp.async double-buffered K/V.
// CTA = 128 queries x 1 head (8 warps x 16 q). 64-key tiles, 2 smem stages.
// Softmax: raw-max tracking, p = ex2((s - m) * C), C = scale*log2(e).
// Dynamic smem: Qs 128x72 + (Ks,Vs)[2] 64x72 each = 55296 B.
// ---------------------------------------------------------------------------
#define FL_QS   (128 * 72)
#define FL_KVS  (64 * 72)
#define FL_SMEM ((FL_QS + 4 * FL_KVS) * 2)   // bytes

__global__ __launch_bounds__(256) void flash_attn_tc(
    const __half* __restrict__ Qm, const __half* __restrict__ Km,
    const __half* __restrict__ Vm, __half* __restrict__ Om)
{
    extern __shared__ __half fsm[];
    __half* Qs = fsm;                         // [128][72]
    __half* Ks = fsm + FL_QS;                 // [2][64][72]
    __half* Vs = fsm + FL_QS + 2 * FL_KVS;    // [2][64][72]

    const int tid = threadIdx.x;
    const int warp = tid >> 5, lane = tid & 31;
    const int h = blockIdx.y, b = blockIdx.z;
    const int q0 = blockIdx.x * 128;
    const size_t base = (size_t)b * S_LEN * DM + (size_t)h * DK;
    const float C = 0.125f * 1.4426950408889634f;   // scale * log2(e)

    // K/V tile staging: 64 rows x 64 halfs; 4 threads/row, 2 chunks each
    const int kvr = tid >> 2;                 // 0..63
    const int kvc = (tid & 3) * 8;            // 0,8,16,24
    auto stage_kv = [&](int st, int k0) {
        #pragma unroll
        for (int i = 0; i < 2; i++) {
            const int cc = kvc + i * 32;
            cp16(sptr(&Ks[st * FL_KVS + kvr * 72 + cc]),
                 &Km[base + (size_t)(k0 + kvr) * DM + cc]);
            cp16(sptr(&Vs[st * FL_KVS + kvr * 72 + cc]),
                 &Vm[base + (size_t)(k0 + kvr) * DM + cc]);
        }
        cp_commit();
    };

    stage_kv(0, 0);
    stage_kv(1, 64);

    // Stage Q (plain loads, once), then hoist per-warp Q A-fragments.
    {
        const int r = tid >> 1;               // 0..127
        const int c0 = (tid & 1) * 32;
        #pragma unroll
        for (int i = 0; i < 4; i++) {
            const int c = c0 + i * 8;
            *(uint4*)&Qs[r * 72 + c] =
                *(const uint4*)&Qm[base + (size_t)(q0 + r) * DM + c];
        }
    }
    __syncthreads();
    uint32_t qf[4][4];
    #pragma unroll
    for (int ks = 0; ks < 4; ks++) {
        const int r = warp * 16 + (lane & 15);
        const int c = ks * 16 + ((lane >> 4) << 3);
        ldm_x4(qf[ks][0], qf[ks][1], qf[ks][2], qf[ks][3], sptr(&Qs[r * 72 + c]));
    }

    float m_[2] = {-1e30f, -1e30f};
    float l_[2] = {0.0f, 0.0f};
    float o[8][4];
    #pragma unroll
    for (int nt = 0; nt < 8; nt++)
        #pragma unroll
        for (int r = 0; r < 4; r++) o[nt][r] = 0.0f;

    const int NT = S_LEN / 64;                // 32

    for (int t = 0; t < NT; t++) {
        cp_wait<1>();                         // tile t arrived (t+1 in flight)
        __syncthreads();
        const int st = t & 1;
        const __half* K_ = Ks + st * FL_KVS;
        const __half* V_ = Vs + st * FL_KVS;

        // ---- scores S = Q . K^T ----
        float s[8][4];
        #pragma unroll
        for (int nt = 0; nt < 8; nt++)
            #pragma unroll
            for (int r = 0; r < 4; r++) s[nt][r] = 0.0f;

        #pragma unroll
        for (int ks = 0; ks < 4; ks++) {
            #pragma unroll
            for (int nt = 0; nt < 8; nt += 2) {
                uint32_t b0, b1, b2, b3;
                const int g = lane >> 3;
                const int rr = nt * 8 + ((g >= 2) ? 8 : 0) + (lane & 7);
                const int cc = ks * 16 + ((g & 1) << 3);
                ldm_x4(b0, b1, b2, b3, sptr(&K_[rr * 72 + cc]));
                mma16816(s[nt], qf[ks], b0, b1);
                mma16816(s[nt + 1], qf[ks], b2, b3);
            }
        }

        // ---- online softmax (raw-domain max; ex2 with fused scale) ----
        float mx0 = -1e30f, mx1 = -1e30f;
        #pragma unroll
        for (int nt = 0; nt < 8; nt++) {
            mx0 = fmaxf(mx0, fmaxf(s[nt][0], s[nt][1]));
            mx1 = fmaxf(mx1, fmaxf(s[nt][2], s[nt][3]));
        }
        #pragma unroll
        for (int off = 1; off <= 2; off <<= 1) {
            mx0 = fmaxf(mx0, __shfl_xor_sync(0xffffffffu, mx0, off));
            mx1 = fmaxf(mx1, __shfl_xor_sync(0xffffffffu, mx1, off));
        }
        const float mn0 = fmaxf(m_[0], mx0);
        const float mn1 = fmaxf(m_[1], mx1);
        const float f0 = ex2((m_[0] - mn0) * C);
        const float f1 = ex2((m_[1] - mn1) * C);
        const float mc0 = mn0 * C, mc1 = mn1 * C;
        float sum0 = 0.0f, sum1 = 0.0f;
        #pragma unroll
        for (int nt = 0; nt < 8; nt++) {
            s[nt][0] = ex2(fmaf(s[nt][0], C, -mc0)); sum0 += s[nt][0];
            s[nt][1] = ex2(fmaf(s[nt][1], C, -mc0)); sum0 += s[nt][1];
            s[nt][2] = ex2(fmaf(s[nt][2], C, -mc1)); sum1 += s[nt][2];
            s[nt][3] = ex2(fmaf(s[nt][3], C, -mc1)); sum1 += s[nt][3];
        }
        #pragma unroll
        for (int off = 1; off <= 2; off <<= 1) {
            sum0 += __shfl_xor_sync(0xffffffffu, sum0, off);
            sum1 += __shfl_xor_sync(0xffffffffu, sum1, off);
        }
        l_[0] = l_[0] * f0 + sum0;
        l_[1] = l_[1] * f1 + sum1;
        m_[0] = mn0; m_[1] = mn1;
        #pragma unroll
        for (int nt = 0; nt < 8; nt++) {
            o[nt][0] *= f0; o[nt][1] *= f0;
            o[nt][2] *= f1; o[nt][3] *= f1;
        }

        // ---- O += P @ V ----
        #pragma unroll
        for (int kt = 0; kt < 4; kt++) {
            uint32_t pa[4];
            pa[0] = pack_h2(s[2 * kt][0],     s[2 * kt][1]);
            pa[1] = pack_h2(s[2 * kt][2],     s[2 * kt][3]);
            pa[2] = pack_h2(s[2 * kt + 1][0], s[2 * kt + 1][1]);
            pa[3] = pack_h2(s[2 * kt + 1][2], s[2 * kt + 1][3]);
            #pragma unroll
            for (int nt = 0; nt < 8; nt += 2) {
                uint32_t b0, b1, b2, b3;
                const int g = lane >> 3;
                const int rr = kt * 16 + ((g & 1) << 3) + (lane & 7);
                const int cc = nt * 8 + ((g >= 2) ? 8 : 0);
                ldm_x4_t(b0, b1, b2, b3, sptr(&V_[rr * 72 + cc]));
                mma16816(o[nt], pa, b0, b1);
                mma16816(o[nt + 1], pa, b2, b3);
            }
        }

        __syncthreads();                      // stage st reads done
        if (t + 2 < NT) stage_kv(st, (t + 2) * 64);
        else cp_commit();
    }

    // ---- epilogue: normalize, write fp16 context ----
    const float inv0 = 1.0f / l_[0];
    const float inv1 = 1.0f / l_[1];
    const int r = q0 + warp * 16 + (lane >> 2);
    #pragma unroll
    for (int nt = 0; nt < 8; nt++) {
        const int c = nt * 8 + ((lane & 3) << 1);
        *(__half2*)&Om[base + (size_t)r * DM + c] =
            __floats2half2_rn(o[nt][0] * inv0, o[nt][1] * inv0);
        *(__half2*)&Om[base + (size_t)(r + 8) * DM + c] =
            __floats2half2_rn(o[nt][2] * inv1, o[nt][3] * inv1);
    }
}

// ---------------------------------------------------------------------------
// Launch pipeline (capture-safe, allocation-free).
// ---------------------------------------------------------------------------
extern "C" void kernel_launch(void* const* d_in, const int* in_sizes, int n_in,
                              void* d_out, int out_size)
{
    const float* q  = (const float*)d_in[0];
    const float* k  = (const float*)d_in[1];
    const float* v  = (const float*)d_in[2];
    const float* Wq = (const float*)d_in[3];
    const float* bq = (const float*)d_in[4];
    const float* Wk = (const float*)d_in[5];
    const float* bk = (const float*)d_in[6];
    const float* Wv = (const float*)d_in[7];
    const float* bv = (const float*)d_in[8];
    const float* Wo = (const float*)d_in[9];
    const float* bo = (const float*)d_in[10];
    float* out = (float*)d_out;

    __half *qh, *kh, *vh, *Wqh, *Wkh, *Wvh, *Woh, *Qh, *Kh, *Vh, *Ch;
    cudaGetSymbolAddress((void**)&qh,  g_qh);
    cudaGetSymbolAddress((void**)&kh,  g_kh);
    cudaGetSymbolAddress((void**)&vh,  g_vh);
    cudaGetSymbolAddress((void**)&Wqh, g_Wqh);
    cudaGetSymbolAddress((void**)&Wkh, g_Wkh);
    cudaGetSymbolAddress((void**)&Wvh, g_Wvh);
    cudaGetSymbolAddress((void**)&Woh, g_Woh);
    cudaGetSymbolAddress((void**)&Qh,  g_Qh);
    cudaGetSymbolAddress((void**)&Kh,  g_Kh);
    cudaGetSymbolAddress((void**)&Vh,  g_Vh);
    cudaGetSymbolAddress((void**)&Ch,  g_Ch);

    static bool attr_done = false;
    if (!attr_done) {
        cudaFuncSetAttribute(gemm_bias_tc<true>,
                             cudaFuncAttributeMaxDynamicSharedMemorySize, GEMM_SMEM);
        cudaFuncSetAttribute(gemm_bias_tc<false>,
                             cudaFuncAttributeMaxDynamicSharedMemorySize, GEMM_SMEM);
        cudaFuncSetAttribute(flash_attn_tc,
                             cudaFuncAttributeMaxDynamicSharedMemorySize, FL_SMEM);
        attr_done = true;
    }

    const int nAct4 = ROWS * DM / 4;
    const int nW4   = DM * DM / 4;
    f2h<<<(nAct4 + 255) / 256, 256>>>((const float4*)q,  (__half2*)qh,  nAct4);
    f2h<<<(nAct4 + 255) / 256, 256>>>((const float4*)k,  (__half2*)kh,  nAct4);
    f2h<<<(nAct4 + 255) / 256, 256>>>((const float4*)v,  (__half2*)vh,  nAct4);
    f2h<<<(nW4 + 255) / 256, 256>>>((const float4*)Wq, (__half2*)Wqh, nW4);
    f2h<<<(nW4 + 255) / 256, 256>>>((const float4*)Wk, (__half2*)Wkh, nW4);
    f2h<<<(nW4 + 255) / 256, 256>>>((const float4*)Wv, (__half2*)Wvh, nW4);
    f2h<<<(nW4 + 255) / 256, 256>>>((const float4*)Wo, (__half2*)Woh, nW4);

    dim3 blk(256);
    dim3 gproj(DM / 128, ROWS / 128);   // (8, 32)
    gemm_bias_tc<true><<<gproj, blk, GEMM_SMEM>>>(qh, Wqh, bq, Qh, ROWS, DM, DM);
    gemm_bias_tc<true><<<gproj, blk, GEMM_SMEM>>>(kh, Wkh, bk, Kh, ROWS, DM, DM);
    gemm_bias_tc<true><<<gproj, blk, GEMM_SMEM>>>(vh, Wvh, bv, Vh, ROWS, DM, DM);

    dim3 gfl(S_LEN / 128, NH, B_SZ);    // (16, 16, 2)
    flash_attn_tc<<<gfl, blk, FL_SMEM>>>(Qh, Kh, Vh, Ch);

    gemm_bias_tc<false><<<gproj, blk, GEMM_SMEM>>>(Ch, Woh, bo, out, ROWS, DM, DM);
}